// round 2
// baseline (speedup 1.0000x reference)
#include <cuda_runtime.h>
#include <cuda_fp16.h>

// LSTMPredictor: B=256, T=1024, HID=150, input feature dim = 1, future = 0.
// Design: 128 persistent CTAs, each owns 2 batch rows for all 1024 timesteps.
// W_hh cached in shared memory as fp16 (180 KB); hidden state kept as an
// interleaved fp16 buffer for the dot phase and fp32 for the output reduction.
// Inner loop packs along K: HFMA2 with (even-k, odd-k) partial sums, flushed to
// fp32 every 30 k to bound accumulation error. Nonlinearities via MUFU
// (EX2/RCP) based sigmoid/tanh (~1e-6 rel err).

namespace {

constexpr int HID  = 150;
constexpr int G4   = 600;     // 4*HID
constexpr int TT   = 1024;
constexpr int NCTA = 128;     // 2 batches per CTA -> 256
constexpr int NTHR = 608;     // 19 warps; 600 active in dot phase
constexpr int KP   = 75;      // k-pairs (HID/2)

// Shared memory layout (bytes)
constexpr int OFF_WTS   = 0;        // fp16 W_hh [600][150], row-major: 180000 B
constexpr int OFF_HKB   = 180000;   // interleaved fp16 h: [75 kpairs][b0k,b0k1,b1k,b1k1] = 600 B
constexpr int OFF_GATES = 180608;   // fp32 gates [2][600] = 4800 B
constexpr int OFF_HBUF  = 185408;   // fp32 h [2][150] = 1200 B
constexpr int OFF_WLIN  = 186608;   // fp32 W_lin [150] = 600 B
constexpr int OFF_X     = 187208;   // fp32 x[2] = 8 B
constexpr int SMEM_BYTES = 187232;

__device__ __forceinline__ float sigf(float x) {
    // 1 / (1 + e^-x): EX2 + RCP MUFUs, ~1e-6 rel err
    return __fdividef(1.0f, 1.0f + __expf(-x));
}
__device__ __forceinline__ float tanhfast(float x) {
    // 1 - 2/(e^{2x}+1): exact limits at +-inf, ~1e-6 rel err
    return 1.0f - __fdividef(2.0f, __expf(2.0f * x) + 1.0f);
}

} // namespace

__global__ void __launch_bounds__(NTHR, 1)
lstm_pred_kernel(const float* __restrict__ input,   // [256][1024]
                 const float* __restrict__ W_ih,    // [600][1]
                 const float* __restrict__ W_hh,    // [600][150]
                 const float* __restrict__ b_ih,    // [600]
                 const float* __restrict__ b_hh,    // [600]
                 const float* __restrict__ W_lin,   // [1][150]
                 const float* __restrict__ b_lin,   // [1]
                 float* __restrict__ out)           // [256][1024]
{
    extern __shared__ char smem[];
    __half*  wts    = reinterpret_cast<__half*>(smem + OFF_WTS);
    __half*  hkb_h  = reinterpret_cast<__half*>(smem + OFF_HKB);
    float2*  hkb2   = reinterpret_cast<float2*>(smem + OFF_HKB);
    float*   gates  = reinterpret_cast<float*>(smem + OFF_GATES);
    float*   hbuf   = reinterpret_cast<float*>(smem + OFF_HBUF);
    float*   wlin_s = reinterpret_cast<float*>(smem + OFF_WLIN);
    float*   x_s    = reinterpret_cast<float*>(smem + OFF_X);

    const int tid = threadIdx.x;
    const int b0  = blockIdx.x * 2;

    // ---- init: convert W_hh to fp16 smem, stage W_lin, zero h, prime x ----
    for (int i = tid; i < G4 * HID; i += NTHR)
        wts[i] = __float2half(W_hh[i]);
    for (int i = tid; i < HID; i += NTHR)
        wlin_s[i] = W_lin[i];
    for (int i = tid; i < KP * 2; i += NTHR)
        reinterpret_cast<unsigned*>(hkb_h)[i] = 0u;
    if (tid < 2) x_s[tid] = input[(b0 + tid) * TT];

    float wih_r = 0.f, bias_r = 0.f;
    if (tid < G4) { wih_r = W_ih[tid]; bias_r = b_ih[tid] + b_hh[tid]; }
    float creg = 0.f;                 // cell state, owned by update threads
    const float blin = b_lin[0];

    const __half2* wrow =
        reinterpret_cast<const __half2*>(wts + (tid < G4 ? tid : 0) * HID);

    __syncthreads();

    for (int t = 0; t < TT; ++t) {
        // ---- phase A: gate preactivations (600 threads, 1 gate row each) ----
        if (tid < G4) {
            __half2 a0 = __float2half2_rn(0.f);
            __half2 a1 = a0;
            float g0 = 0.f, g1 = 0.f;
#pragma unroll
            for (int p = 0; p < KP; ++p) {
                __half2 w2 = wrow[p];                  // LDS.32, conflict-free
                float2  hv = hkb2[p];                  // LDS.64 broadcast
                __half2 h0 = *reinterpret_cast<const __half2*>(&hv.x);
                __half2 h1 = *reinterpret_cast<const __half2*>(&hv.y);
                a0 = __hfma2(w2, h0, a0);
                a1 = __hfma2(w2, h1, a1);
                if ((p % 15) == 14) {                  // fp32 flush every 30 k
                    float2 f0 = __half22float2(a0);
                    float2 f1 = __half22float2(a1);
                    g0 += f0.x + f0.y;
                    g1 += f1.x + f1.y;
                    a0 = __float2half2_rn(0.f);
                    a1 = a0;
                }
            }
            g0 += fmaf(x_s[0], wih_r, bias_r);
            g1 += fmaf(x_s[1], wih_r, bias_r);
            gates[tid]      = g0;
            gates[G4 + tid] = g1;
        }
        __syncthreads();

        // ---- phase B: cell update (300 threads: (hidden j, batch b)) ----
        if (tid < 2 * HID) {
            const int bb = (tid >= HID) ? 1 : 0;
            const int j  = tid - bb * HID;
            const float* gb = gates + bb * G4;
            float si = sigf(gb[j]);
            float sf = sigf(gb[HID + j]);
            float tg = tanhfast(gb[2 * HID + j]);
            float so = sigf(gb[3 * HID + j]);
            float cn = fmaf(sf, creg, si * tg);
            creg = cn;
            float hn = so * tanhfast(cn);
            hbuf[bb * HID + j] = hn;
            hkb_h[(j >> 1) * 4 + bb * 2 + (j & 1)] = __float2half(hn);
        } else if (tid == 2 * HID) {
            if (t + 1 < TT) x_s[0] = input[b0 * TT + t + 1];
        } else if (tid == 2 * HID + 1) {
            if (t + 1 < TT) x_s[1] = input[(b0 + 1) * TT + t + 1];
        }
        __syncthreads();

        // ---- phase C: output projection (warps 0,1), overlaps next phase A
        // of the other 17 warps; hbuf stable until after next BAR1.
        if (tid < 64) {
            const int bb   = tid >> 5;
            const int lane = tid & 31;
            float s = 0.f;
#pragma unroll
            for (int m = 0; m < 5; ++m) {
                int j = lane + 32 * m;
                if (j < HID) s = fmaf(hbuf[bb * HID + j], wlin_s[j], s);
            }
#pragma unroll
            for (int off = 16; off; off >>= 1)
                s += __shfl_down_sync(0xffffffffu, s, off);
            if (lane == 0) out[(b0 + bb) * TT + t] = s + blin;
        }
    }
}

extern "C" void kernel_launch(void* const* d_in, const int* in_sizes, int n_in,
                              void* d_out, int out_size) {
    const float* input = (const float*)d_in[0];
    const float* W_ih  = (const float*)d_in[1];
    const float* W_hh  = (const float*)d_in[2];
    const float* b_ih  = (const float*)d_in[3];
    const float* b_hh  = (const float*)d_in[4];
    const float* W_lin = (const float*)d_in[5];
    const float* b_lin = (const float*)d_in[6];
    // d_in[7] (future) is a static 0 in this problem; ignored.
    float* out = (float*)d_out;

    cudaFuncSetAttribute(lstm_pred_kernel,
                         cudaFuncAttributeMaxDynamicSharedMemorySize, SMEM_BYTES);
    lstm_pred_kernel<<<NCTA, NTHR, SMEM_BYTES>>>(input, W_ih, W_hh, b_ih, b_hh,
                                                 W_lin, b_lin, out);
}

// round 3
// speedup vs baseline: 1.0479x; 1.0479x over previous
#include <cuda_runtime.h>
#include <cuda_fp16.h>

// LSTMPredictor: B=256, T=1024, HID=150, input dim 1, future=0.
// R3: 128 persistent CTAs x 320 threads (10 warps), 2 batch rows per CTA.
// Phase A: 300 threads, thread q owns gate rows (q, 300+q) -> (i_j,g_j) for
// q=j<150, (f_j,o_j) for q=150+j. Weights fp16 in smem, rows padded to 152
// halves; all smem traffic via LDS.128 (weights: 4 full 128B wavefronts,
// h: 1 broadcast wavefront). The (i,g)/(f,o) pairing fuses the gate
// nonlinearity split: only a 150x2 float "a = sig(i)*tanh(g)" exchange.
// fp32 flush of HFMA2 accumulators every 32 halves bounds error (~4e-5).

namespace {

constexpr int HID  = 150;
constexpr int TT   = 1024;
constexpr int NCTA = 128;
constexpr int NTHR = 320;
constexpr int RP   = 152;   // padded row length (halves), 304 B, 19 x 16 B
constexpr int NIT  = 19;    // LDS.128 iterations (8 halves each)

// Shared memory layout (bytes); all 16B-aligned where needed.
constexpr int OFF_WTS  = 0;                      // fp16 [600][152] = 182400
constexpr int OFF_HK   = 182400;                 // fp16 h [2][152] = 608
constexpr int OFF_AS   = 183008;                 // fp32 a  [2][152] = 1216
constexpr int OFF_HBUF = 184224;                 // fp32 h  [2][152] = 1216
constexpr int OFF_WLIN = 185440;                 // fp32 [152] = 608
constexpr int OFF_X    = 186048;                 // fp32 x[2]
constexpr int SMEM_BYTES = 186080;

__device__ __forceinline__ float sigf(float x) {
    return __fdividef(1.0f, 1.0f + __expf(-x));
}
__device__ __forceinline__ float tanhfast(float x) {
    return 1.0f - __fdividef(2.0f, __expf(2.0f * x) + 1.0f);
}

__device__ __forceinline__ void fma8(const uint4& w, const uint4& h,
                                     __half2& acc) {
    const __half2* wp = reinterpret_cast<const __half2*>(&w);
    const __half2* hp = reinterpret_cast<const __half2*>(&h);
    acc = __hfma2(wp[0], hp[0], acc);
    acc = __hfma2(wp[1], hp[1], acc);
    acc = __hfma2(wp[2], hp[2], acc);
    acc = __hfma2(wp[3], hp[3], acc);
}

} // namespace

__global__ void __launch_bounds__(NTHR, 1)
lstm_pred_kernel(const float* __restrict__ input,   // [256][1024]
                 const float* __restrict__ W_ih,    // [600][1]
                 const float* __restrict__ W_hh,    // [600][150]
                 const float* __restrict__ b_ih,    // [600]
                 const float* __restrict__ b_hh,    // [600]
                 const float* __restrict__ W_lin,   // [1][150]
                 const float* __restrict__ b_lin,   // [1]
                 float* __restrict__ out)           // [256][1024]
{
    extern __shared__ char smem[];
    __half* wts    = reinterpret_cast<__half*>(smem + OFF_WTS);
    __half* hk     = reinterpret_cast<__half*>(smem + OFF_HK);    // [2][152]
    float*  a_s    = reinterpret_cast<float*>(smem + OFF_AS);     // [2][152]
    float*  hbuf   = reinterpret_cast<float*>(smem + OFF_HBUF);   // [2][152]
    float*  wlin_s = reinterpret_cast<float*>(smem + OFF_WLIN);
    float*  x_s    = reinterpret_cast<float*>(smem + OFF_X);

    const int tid = threadIdx.x;
    const int b0  = blockIdx.x * 2;

    // ---- init ----
    // Weights -> fp16 smem, rows padded to RP halves; pads MUST be 0
    // (they multiply h pads; garbage could be NaN and 0*NaN = NaN).
    for (int i = tid; i < 600 * RP; i += NTHR) {
        const int r = i / RP, c = i - r * RP;
        wts[i] = (c < HID) ? __float2half(W_hh[r * HID + c]) : __half(0);
    }
    for (int i = tid; i < HID; i += NTHR) wlin_s[i] = W_lin[i];
    for (int i = tid; i < 2 * RP; i += NTHR) hk[i] = __half(0);   // incl pads
    if (tid < 2) x_s[tid] = input[(b0 + tid) * TT];

    const int q = tid;                     // row-pair owner if q < 300
    float wihA = 0.f, wihB = 0.f, biasA = 0.f, biasB = 0.f;
    if (q < 300) {
        wihA  = W_ih[q];
        wihB  = W_ih[300 + q];
        biasA = b_ih[q] + b_hh[q];
        biasB = b_ih[300 + q] + b_hh[300 + q];
    }
    float c0 = 0.f, c1 = 0.f;              // cell state (f/o threads, q>=150)
    const float blin = b_lin[0];

    const uint4* rowA = reinterpret_cast<const uint4*>(wts + (q < 300 ? q : 0) * RP);
    const uint4* rowB = reinterpret_cast<const uint4*>(wts + (q < 300 ? 300 + q : 300) * RP);
    const uint4* hk0v = reinterpret_cast<const uint4*>(hk);
    const uint4* hk1v = reinterpret_cast<const uint4*>(hk + RP);

    __syncthreads();

    for (int t = 0; t < TT; ++t) {
        float gA0, gA1, gB0, gB1;
        // ---- phase A: two gate-row dot products over shared h ----
        if (q < 300) {
            __half2 z = __float2half2_rn(0.f);
            __half2 aA0 = z, aA1 = z, aB0 = z, aB1 = z;
            gA0 = gA1 = gB0 = gB1 = 0.f;
#pragma unroll
            for (int it = 0; it < NIT; ++it) {
                const uint4 w4A = rowA[it];      // LDS.128, conflict-free
                const uint4 w4B = rowB[it];
                const uint4 h40 = hk0v[it];      // LDS.128 broadcast
                const uint4 h41 = hk1v[it];
                fma8(w4A, h40, aA0);
                fma8(w4A, h41, aA1);
                fma8(w4B, h40, aB0);
                fma8(w4B, h41, aB1);
                if ((it & 3) == 3 || it == NIT - 1) {   // fp32 flush
                    float2 f;
                    f = __half22float2(aA0); gA0 += f.x + f.y; aA0 = z;
                    f = __half22float2(aA1); gA1 += f.x + f.y; aA1 = z;
                    f = __half22float2(aB0); gB0 += f.x + f.y; aB0 = z;
                    f = __half22float2(aB1); gB1 += f.x + f.y; aB1 = z;
                }
            }
            const float x0 = x_s[0], x1 = x_s[1];
            gA0 += fmaf(x0, wihA, biasA);
            gA1 += fmaf(x1, wihA, biasA);
            gB0 += fmaf(x0, wihB, biasB);
            gB1 += fmaf(x1, wihB, biasB);
            if (q < HID) {                  // (i,g) threads: a = sig(i)tanh(g)
                a_s[q]      = sigf(gA0) * tanhfast(gB0);
                a_s[RP + q] = sigf(gA1) * tanhfast(gB1);
            }
        }
        __syncthreads();

        // ---- phase B: (f,o) threads finish the cell update ----
        if (q >= HID && q < 2 * HID) {
            const int j = q - HID;
            c0 = fmaf(sigf(gA0), c0, a_s[j]);
            c1 = fmaf(sigf(gA1), c1, a_s[RP + j]);
            const float h0 = sigf(gB0) * tanhfast(c0);
            const float h1 = sigf(gB1) * tanhfast(c1);
            hbuf[j]      = h0;
            hbuf[RP + j] = h1;
            hk[j]        = __float2half(h0);
            hk[RP + j]   = __float2half(h1);
        } else if (q == 300) {
            if (t + 1 < TT) x_s[0] = input[b0 * TT + t + 1];
        } else if (q == 301) {
            if (t + 1 < TT) x_s[1] = input[(b0 + 1) * TT + t + 1];
        }
        __syncthreads();

        // ---- phase C: output projection (warps 0,1), overlaps next phase A
        // of the other warps; hbuf is stable until after the next BAR1.
        if (tid < 64) {
            const int bb   = tid >> 5;
            const int lane = tid & 31;
            float s = 0.f;
#pragma unroll
            for (int m = 0; m < 5; ++m) {
                const int j = lane + 32 * m;
                if (j < HID) s = fmaf(hbuf[bb * RP + j], wlin_s[j], s);
            }
#pragma unroll
            for (int off = 16; off; off >>= 1)
                s += __shfl_down_sync(0xffffffffu, s, off);
            if (lane == 0) out[(b0 + bb) * TT + t] = s + blin;
        }
    }
}

extern "C" void kernel_launch(void* const* d_in, const int* in_sizes, int n_in,
                              void* d_out, int out_size) {
    const float* input = (const float*)d_in[0];
    const float* W_ih  = (const float*)d_in[1];
    const float* W_hh  = (const float*)d_in[2];
    const float* b_ih  = (const float*)d_in[3];
    const float* b_hh  = (const float*)d_in[4];
    const float* W_lin = (const float*)d_in[5];
    const float* b_lin = (const float*)d_in[6];
    float* out = (float*)d_out;

    cudaFuncSetAttribute(lstm_pred_kernel,
                         cudaFuncAttributeMaxDynamicSharedMemorySize, SMEM_BYTES);
    lstm_pred_kernel<<<NCTA, NTHR, SMEM_BYTES>>>(input, W_ih, W_hh, b_ih, b_hh,
                                                 W_lin, b_lin, out);
}